// round 13
// baseline (speedup 1.0000x reference)
#include <cuda_runtime.h>
#include <cuda_bf16.h>
#include <float.h>

#define Bn 128
#define On 1024
#define In 1024
#define EPSc 1e-7f
#define L2E 1.4426950408889634f
#define CUT_NATS 20.794415417f   // 30*ln2: drop softmax terms with weight < 2^-30
#define CAP 96                   // per-warp candidate capacity (dense fallback beyond)

// Scratch (no allocs allowed) — fully rewritten every run, no cross-run state.
__device__ float g_c2_im[In * On];    // C^2, i-major [i][o]
__device__ float g_tmin[In * 32];     // per (i, 32-o tile) min of C^2
__device__ float g_data_im[In * Bn];  // data transposed [i][b]

__device__ __forceinline__ float rsq(float x) {
    float r;
    asm("rsqrt.approx.ftz.f32 %0, %1;" : "=f"(r) : "f"(x));
    return r;
}
__device__ __forceinline__ float ex2(float x) {
    float r;
    asm("ex2.approx.ftz.f32 %0, %1;" : "=f"(r) : "f"(x));
    return r;
}

// ---------------- kprep: C^2 transpose + per-tile min + data transpose + zeroing ----
// Launch 1 of 2. Keeps IEEE div.rn for ix/iy, ox/oy — C is cancellation-amplified.
__global__ void kprep(float* __restrict__ out,
                      const float* __restrict__ data,
                      const float* __restrict__ ix, const float* __restrict__ iy,
                      const float* __restrict__ ox, const float* __restrict__ oy,
                      const float* __restrict__ la, const float* __restrict__ lm) {
    __shared__ float tile[32][33];
    int tx = threadIdx.x & 31;
    int ty = threadIdx.x >> 5;

    if (blockIdx.x < 1024) {
        int otile = blockIdx.x & 31;
        int ob  = otile * 32;               // o tile base
        int ibt = (blockIdx.x >> 5) * 32;   // i tile base
#pragma unroll
        for (int k = 0; k < 4; k++) {
            int o = ob + ty + k * 8;
            int idx = o * In + ibt + tx;    // coalesced over tx
            float c = (ix[idx] / iy[idx] + la[idx]) * (1.0f + lm[idx]) - ox[idx] / oy[idx];
            tile[ty + k * 8][tx] = c * c;
        }
        __syncthreads();
#pragma unroll
        for (int k = 0; k < 4; k++) {
            int il = ty + k * 8;            // i within tile (fixed per warp per k)
            float v = tile[tx][il];         // tx = o within tile
            g_c2_im[(ibt + il) * In + ob + tx] = v;
            float mn = v;                   // min over the 32 o's of this tile
#pragma unroll
            for (int s = 16; s; s >>= 1) mn = fminf(mn, __shfl_xor_sync(0xffffffffu, mn, s));
            if (tx == 0) g_tmin[(ibt + il) * 32 + otile] = mn;
        }
    } else {
        // data transpose [128,1024] -> [1024,128], plus output zeroing
        int tb = blockIdx.x - 1024;         // 0..127
        ((float4*)out)[tb * 256 + threadIdx.x] = make_float4(0.f, 0.f, 0.f, 0.f);
        int bb = (tb & 3) * 32;
        int ib = (tb >> 2) * 32;
#pragma unroll
        for (int k = 0; k < 4; k++)
            tile[ty + k * 8][tx] = data[(bb + ty + k * 8) * In + ib + tx];
        __syncthreads();
#pragma unroll
        for (int k = 0; k < 4; k++) {
            int il = ty + k * 8;
            g_data_im[(ib + il) * Bn + bb + tx] = tile[tx][il];
        }
    }
}

// ---------------- kmega: hierarchical sparse softmax (launch 2 of 2) ----------------
// 2048 warps; warp = (i, half). Each warp: 128B tile-min load -> c2min -> T over
// its 64 b's -> select tiles (usually 1-2) -> load only those (128B each) ->
// exact check -> evaluate ~3 candidates for 64 b's -> scatter-add.
__global__ void __launch_bounds__(256) kmega(float* __restrict__ out) {
    __shared__ int   s_o[8][CAP];
    __shared__ float s_c2[8][CAP];

    int t = threadIdx.x, lane = t & 31, warp = t >> 5;
    int gw = blockIdx.x * 8 + warp;
    int i = gw >> 1;
    int half = gw & 1;                      // which 64 b's
    unsigned lmask = (1u << lane) - 1u;

    // --- tile mins: one 128B coalesced load ---
    float tmin = g_tmin[i * 32 + lane];
    float mn = tmin;
#pragma unroll
    for (int s = 16; s; s >>= 1) mn = fminf(mn, __shfl_xor_sync(0xffffffffu, mn, s));
    float c2min = mn;

    // --- per-b scalars (b = 64*half + lane + 32r) + keep threshold ---
    const float* dcol = g_data_im + (size_t)i * Bn + 64 * half;
    float dd[2], g2[2], Bm[2];
    float kmax = 0.f;
#pragma unroll
    for (int r = 0; r < 2; r++) {
        dd[r] = dcol[lane + 32 * r];        // coalesced
        float g = 1.0f / (1.0f + __expf(-dd[r]));
        g2[r] = g * g;
        float smax = rsq(fmaf(c2min, g2[r], EPSc));
        Bm[r] = -smax * L2E;
        float q = smax - CUT_NATS;
        float keep = (q > 0.f) ? (1.0f / (q * q) - EPSc) / g2[r] : FLT_MAX;
        kmax = fmaxf(kmax, keep);
    }
#pragma unroll
    for (int s = 16; s; s >>= 1) kmax = fmaxf(kmax, __shfl_xor_sync(0xffffffffu, kmax, s));
    float T = kmax;                          // conservative for THIS warp's 64 b's

    // --- select candidate tiles, then exact-check only those ---
    unsigned selmask = __ballot_sync(0xffffffffu, tmin <= T);
    const float* row = g_c2_im + (size_t)i * In;
    int base = 0;
    unsigned m = selmask;
    while (m) {
        int ot = __ffs(m) - 1;              // warp-uniform
        m &= m - 1;
        float v = row[ot * 32 + lane];      // 128B coalesced
        bool pred = (v <= T);
        unsigned bal = __ballot_sync(0xffffffffu, pred);
        if (pred) {
            int pos = base + __popc(bal & lmask);
            if (pos < CAP) {
                s_o[warp][pos]  = ot * 32 + lane;
                s_c2[warp][pos] = v;
            }
        }
        base += __popc(bal);
    }
    int cnt = base;
    __syncwarp();

    if (cnt <= CAP) {
        // --- sparse path: lanes walk the shared tiny list (LDS broadcast) ---
        float S[2] = {0.f, 0.f};
        for (int k = 0; k < cnt; k++) {
            float c2 = s_c2[warp][k];
#pragma unroll
            for (int r = 0; r < 2; r++)
                S[r] += ex2(fmaf(rsq(fmaf(c2, g2[r], EPSc)), L2E, Bm[r]));
        }
        float coef[2];
#pragma unroll
        for (int r = 0; r < 2; r++) coef[r] = __fdividef(dd[r], S[r]);
        for (int k = 0; k < cnt; k++) {
            int o = s_o[warp][k];
            float c2 = s_c2[warp][k];
#pragma unroll
            for (int r = 0; r < 2; r++) {
                float e = ex2(fmaf(rsq(fmaf(c2, g2[r], EPSc)), L2E, Bm[r]));
                atomicAdd(&out[(size_t)(64 * half + lane + 32 * r) * On + o], coef[r] * e);
            }
        }
    } else {
        // --- dense fallback: full row (correct for any data; never taken in practice) ---
        float S[2] = {0.f, 0.f};
        for (int k = 0; k < In; k++) {
            float c2 = row[k];
#pragma unroll
            for (int r = 0; r < 2; r++)
                S[r] += ex2(fmaf(rsq(fmaf(c2, g2[r], EPSc)), L2E, Bm[r]));
        }
        float coef[2];
#pragma unroll
        for (int r = 0; r < 2; r++) coef[r] = __fdividef(dd[r], S[r]);
        for (int k = 0; k < In; k++) {
            float c2 = row[k];
#pragma unroll
            for (int r = 0; r < 2; r++) {
                float e = ex2(fmaf(rsq(fmaf(c2, g2[r], EPSc)), L2E, Bm[r]));
                atomicAdd(&out[(size_t)(64 * half + lane + 32 * r) * On + k], coef[r] * e);
            }
        }
    }
}

extern "C" void kernel_launch(void* const* d_in, const int* in_sizes, int n_in,
                              void* d_out, int out_size) {
    const float* data = (const float*)d_in[0];
    const float* ix   = (const float*)d_in[1];
    const float* iy   = (const float*)d_in[2];
    const float* ox   = (const float*)d_in[3];
    const float* oy   = (const float*)d_in[4];
    const float* la   = (const float*)d_in[5];
    const float* lm   = (const float*)d_in[6];
    float* out = (float*)d_out;

    kprep<<<1152, 256>>>(out, data, ix, iy, ox, oy, la, lm);
    kmega<<<256, 256>>>(out);
}